// round 2
// baseline (speedup 1.0000x reference)
#include <cuda_runtime.h>
#include <math.h>

#define TT 2048
#define HH 4096
#define NH 32
#define HD 128
#define II 11008
#define ATTN_TOPK 16
#define MLP_TOPK 2048

// ---------------- scratch (static device allocations only) ----------------
__device__ float g_hs[TT * HH];        // ln1 out, later reused for ln2 out
__device__ float g_q[TT * HH];
__device__ float g_k[TT * HH];
__device__ float g_v[TT * HH];
__device__ float g_attn[TT * HH];
__device__ float g_res2[TT * HH];
__device__ float g_hlogit[TT * NH];
__device__ float g_headmask[TT * NH];
__device__ float g_mlogit[TT * II];
__device__ float g_fcmask[TT * II];
__device__ float g_gate[TT * II];
__device__ float g_up[TT * II];

// ---------------- RMSNorm ----------------
__global__ void rmsnorm_kernel(const float* __restrict__ x,
                               const float* __restrict__ w,
                               float* __restrict__ out) {
    int row = blockIdx.x;
    const float4* x4 = (const float4*)(x + (size_t)row * HH);
    const float4* w4 = (const float4*)w;
    float s = 0.f;
    for (int i = threadIdx.x; i < HH / 4; i += 256) {
        float4 v = x4[i];
        s += v.x * v.x + v.y * v.y + v.z * v.z + v.w * v.w;
    }
    __shared__ float red[256];
    red[threadIdx.x] = s;
    __syncthreads();
    for (int o = 128; o > 0; o >>= 1) {
        if (threadIdx.x < o) red[threadIdx.x] += red[threadIdx.x + o];
        __syncthreads();
    }
    float rs = rsqrtf(red[0] / (float)HH + 1e-6f);
    float4* o4 = (float4*)(out + (size_t)row * HH);
    for (int i = threadIdx.x; i < HH / 4; i += 256) {
        float4 a = x4[i];
        float4 ww = w4[i];
        a.x = a.x * rs * ww.x;
        a.y = a.y * rs * ww.y;
        a.z = a.z * rs * ww.z;
        a.w = a.w * rs * ww.w;
        o4[i] = a;
    }
}

// ---------------- SGEMM: C[M,N] = A[M,K] * B[N,K]^T (+bias[N]) (+addsrc[M,N]) ----------------
// BM=BN=128, BK=16, 256 threads, 8x8 per thread. M%128==0, N%128==0, K%16==0.
__global__ void __launch_bounds__(256) sgemm_nt_kernel(
    const float* __restrict__ A, const float* __restrict__ B,
    const float* __restrict__ bias, const float* __restrict__ addsrc,
    float* __restrict__ C, int M, int N, int K) {
    __shared__ float As[16][132];
    __shared__ float Bs[16][132];
    const int bm = blockIdx.y * 128;
    const int bn = blockIdx.x * 128;
    const int tid = threadIdx.x;
    const int tr = tid >> 4;   // 0..15
    const int tc = tid & 15;   // 0..15

    float acc[8][8];
#pragma unroll
    for (int i = 0; i < 8; i++)
#pragma unroll
        for (int j = 0; j < 8; j++) acc[i][j] = 0.f;

    const int lr = tid >> 2;        // 0..63
    const int lc = (tid & 3) * 4;   // 0,4,8,12
    const float* Aptr = A + (size_t)(bm + lr) * K + lc;
    const float* Bptr = B + (size_t)(bn + lr) * K + lc;
    const size_t rowoff = (size_t)64 * K;

    for (int k0 = 0; k0 < K; k0 += 16) {
        float4 a0 = *(const float4*)(Aptr + k0);
        float4 a1 = *(const float4*)(Aptr + k0 + rowoff);
        float4 b0 = *(const float4*)(Bptr + k0);
        float4 b1 = *(const float4*)(Bptr + k0 + rowoff);
        As[lc + 0][lr] = a0.x; As[lc + 1][lr] = a0.y;
        As[lc + 2][lr] = a0.z; As[lc + 3][lr] = a0.w;
        As[lc + 0][lr + 64] = a1.x; As[lc + 1][lr + 64] = a1.y;
        As[lc + 2][lr + 64] = a1.z; As[lc + 3][lr + 64] = a1.w;
        Bs[lc + 0][lr] = b0.x; Bs[lc + 1][lr] = b0.y;
        Bs[lc + 2][lr] = b0.z; Bs[lc + 3][lr] = b0.w;
        Bs[lc + 0][lr + 64] = b1.x; Bs[lc + 1][lr + 64] = b1.y;
        Bs[lc + 2][lr + 64] = b1.z; Bs[lc + 3][lr + 64] = b1.w;
        __syncthreads();
#pragma unroll
        for (int kk = 0; kk < 16; kk++) {
            float ra[8], rb[8];
#pragma unroll
            for (int i = 0; i < 8; i++) ra[i] = As[kk][tr * 8 + i];
#pragma unroll
            for (int j = 0; j < 8; j++) rb[j] = Bs[kk][tc * 8 + j];
#pragma unroll
            for (int i = 0; i < 8; i++)
#pragma unroll
                for (int j = 0; j < 8; j++)
                    acc[i][j] = fmaf(ra[i], rb[j], acc[i][j]);
        }
        __syncthreads();
    }

#pragma unroll
    for (int i = 0; i < 8; i++) {
        int row = bm + tr * 8 + i;
        size_t base = (size_t)row * N + bn + tc * 8;
#pragma unroll
        for (int j = 0; j < 8; j += 4) {
            float4 r;
            r.x = acc[i][j + 0]; r.y = acc[i][j + 1];
            r.z = acc[i][j + 2]; r.w = acc[i][j + 3];
            if (bias) {
                int cn = bn + tc * 8 + j;
                r.x += bias[cn + 0]; r.y += bias[cn + 1];
                r.z += bias[cn + 2]; r.w += bias[cn + 3];
            }
            if (addsrc) {
                float4 s = *(const float4*)(addsrc + base + j);
                r.x += s.x; r.y += s.y; r.z += s.z; r.w += s.w;
            }
            *(float4*)(C + base + j) = r;
        }
    }
}

// ---------------- RoPE (applied in-place to q and k) ----------------
// NOTE: position_ids is int32 on the wire (JAX x64 disabled demotes int64->int32).
__global__ void rope_kernel(float* __restrict__ q, float* __restrict__ k,
                            const int* __restrict__ pos) {
    int idx = blockIdx.x * 256 + threadIdx.x;
    if (idx >= TT * NH * 64) return;
    int j = idx & 63;
    int th = idx >> 6;       // t*32 + h
    int t = th >> 5;
    float p = (float)pos[t];
    // inv_freq = theta^{-2j/128} = 2^{-j * log2(10000)/64}
    float ang = p * exp2f(-(float)j * (13.287712379549449f / 64.f));
    float s, c;
    sincosf(ang, &s, &c);
    size_t base = (size_t)th * HD + j;
    float q0 = q[base], q1 = q[base + 64];
    q[base] = q0 * c - q1 * s;
    q[base + 64] = q1 * c + q0 * s;
    float k0 = k[base], k1 = k[base + 64];
    k[base] = k0 * c - k1 * s;
    k[base + 64] = k1 * c + k0 * s;
}

// ---------------- attn predictor logits: [T,32] = hs @ apw^T + apb ----------------
__global__ void attn_pred_kernel(const float* __restrict__ hs,
                                 const float* __restrict__ w,
                                 const float* __restrict__ b,
                                 float* __restrict__ out) {
    int t = blockIdx.x;
    int warp = threadIdx.x >> 5, lane = threadIdx.x & 31;
    const float* hsrow = hs + (size_t)t * HH;
    for (int hh = 0; hh < 4; hh++) {
        int h = warp * 4 + hh;
        const float* wr = w + (size_t)h * HH;
        float s = 0.f;
        for (int kk = lane; kk < HH; kk += 32) s += hsrow[kk] * wr[kk];
        for (int o = 16; o > 0; o >>= 1) s += __shfl_xor_sync(0xffffffffu, s, o);
        if (lane == 0) out[t * NH + h] = s + b[h];
    }
}

// ---------------- head top-16 mask (exact jax top_k tie semantics) ----------------
__global__ void head_mask_kernel(const float* __restrict__ logit,
                                 float* __restrict__ mask) {
    int t = blockIdx.x;
    int h = threadIdx.x;   // 32 threads
    float v = logit[t * NH + h];
    int rank = 0;
    for (int j = 0; j < NH; j++) {
        float vj = logit[t * NH + j];
        rank += (vj > v) || (vj == v && j < h);
    }
    mask[t * NH + h] = (rank < ATTN_TOPK) ? 1.f : 0.f;
}

// ---------------- attention: one block per (q-row, head); skip masked heads ----------------
__global__ void attention_kernel(const float* __restrict__ q,
                                 const float* __restrict__ k,
                                 const float* __restrict__ v,
                                 const float* __restrict__ hmask,
                                 const int* __restrict__ amask,
                                 float* __restrict__ out) {
    int t = blockIdx.x, h = blockIdx.y, tid = threadIdx.x;  // 128 threads
    size_t obase = (size_t)t * HH + h * HD;
    if (hmask[t * NH + h] == 0.f) {
        out[obase + tid] = 0.f;
        return;
    }
    __shared__ float qs[HD];
    __shared__ float p[TT];
    __shared__ float red[128];
    qs[tid] = q[obase + tid] * 0.08838834764831845f;  // 1/sqrt(128)
    __syncthreads();
    int nk = t + 1;
    const float NEGF = -3.4e38f;
    float lm = NEGF;
    for (int j = tid; j < nk; j += 128) {
        float s;
        if (amask[j]) {
            const float4* kr = (const float4*)(k + (size_t)j * HH + h * HD);
            s = 0.f;
#pragma unroll
            for (int d4 = 0; d4 < 32; d4++) {
                float4 kv = kr[d4];
                s += qs[4 * d4 + 0] * kv.x + qs[4 * d4 + 1] * kv.y +
                     qs[4 * d4 + 2] * kv.z + qs[4 * d4 + 3] * kv.w;
            }
        } else {
            s = NEGF;
        }
        p[j] = s;
        lm = fmaxf(lm, s);
    }
    red[tid] = lm;
    __syncthreads();
    for (int o = 64; o > 0; o >>= 1) {
        if (tid < o) red[tid] = fmaxf(red[tid], red[tid + o]);
        __syncthreads();
    }
    float M = red[0];
    __syncthreads();
    float ls = 0.f;
    for (int j = tid; j < nk; j += 128) {
        float e = __expf(p[j] - M);
        p[j] = e;
        ls += e;
    }
    red[tid] = ls;
    __syncthreads();
    for (int o = 64; o > 0; o >>= 1) {
        if (tid < o) red[tid] += red[tid + o];
        __syncthreads();
    }
    float inv = 1.f / red[0];
    __syncthreads();
    float acc = 0.f;
#pragma unroll 4
    for (int j = 0; j < nk; j++)
        acc = fmaf(p[j], v[(size_t)j * HH + h * HD + tid], acc);
    out[obase + tid] = acc * inv;
}

// ---------------- MLP top-2048-of-11008 per row: radix select on monotone keys ----------------
__device__ __forceinline__ unsigned fkey(float x) {
    unsigned b = __float_as_uint(x);
    return (b & 0x80000000u) ? ~b : (b | 0x80000000u);
}

__global__ void mlp_topk_kernel(const float* __restrict__ logits,
                                float* __restrict__ mask) {
    int row = blockIdx.x;
    const float* lr = logits + (size_t)row * II;
    __shared__ unsigned hist[256];
    __shared__ unsigned sh_sel, sh_kk;
    __shared__ unsigned sh_cnt[2];
    int tid = threadIdx.x;
    unsigned prefix = 0;
    unsigned kk = MLP_TOPK;
    for (int shift = 24; shift >= 0; shift -= 8) {
        hist[tid] = 0;
        __syncthreads();
        for (int i = tid; i < II; i += 256) {
            unsigned u = fkey(lr[i]);
            bool ok = (shift == 24) || ((u >> (shift + 8)) == prefix);
            if (ok) atomicAdd(&hist[(u >> shift) & 255u], 1u);
        }
        __syncthreads();
        if (tid == 0) {
            unsigned c = 0;
            int sel = 0;
            for (int b = 255; b >= 0; b--) {
                c += hist[b];
                if (c >= kk) { sel = b; break; }
            }
            sh_sel = (unsigned)sel;
            sh_kk = kk - (c - hist[sel]);
        }
        __syncthreads();
        prefix = (prefix << 8) | sh_sel;
        kk = sh_kk;
        __syncthreads();
    }
    unsigned thresh = prefix;
    if (tid < 2) sh_cnt[tid] = 0;
    __syncthreads();
    unsigned lg = 0, le = 0;
    for (int i = tid; i < II; i += 256) {
        unsigned u = fkey(lr[i]);
        if (u > thresh) lg++;
        else if (u == thresh) le++;
    }
    atomicAdd(&sh_cnt[0], lg);
    atomicAdd(&sh_cnt[1], le);
    __syncthreads();
    unsigned g = sh_cnt[0], e = sh_cnt[1];
    float* mr = mask + (size_t)row * II;
    if (g + e == MLP_TOPK) {
        for (int i = tid; i < II; i += 256)
            mr[i] = (fkey(lr[i]) >= thresh) ? 1.f : 0.f;
    } else {
        // rare tie case: equals selected in index order (jax tie-break)
        for (int i = tid; i < II; i += 256)
            mr[i] = (fkey(lr[i]) > thresh) ? 1.f : 0.f;
        __syncthreads();
        if (tid == 0) {
            unsigned quota = MLP_TOPK - g;
            for (int i = 0; i < II && quota > 0; i++) {
                if (fkey(lr[i]) == thresh) { mr[i] = 1.f; quota--; }
            }
        }
    }
}

// ---------------- inter = silu(gate) * up * mask (in-place into gate) ----------------
__global__ void silu_mul_mask_kernel(float* __restrict__ gate,
                                     const float* __restrict__ up,
                                     const float* __restrict__ mask, int n) {
    int i = blockIdx.x * 256 + threadIdx.x;
    if (i < n) {
        float x = gate[i];
        float si = x / (1.f + __expf(-x));
        gate[i] = si * up[i] * mask[i];
    }
}

// ---------------- launch ----------------
extern "C" void kernel_launch(void* const* d_in, const int* in_sizes, int n_in,
                              void* d_out, int out_size) {
    const float* hidden = (const float*)d_in[0];
    const int* amask = (const int*)d_in[1];
    const int* pos = (const int*)d_in[2];     // int32 (JAX x64 disabled)
    const float* wq = (const float*)d_in[3];
    const float* wk = (const float*)d_in[4];
    const float* wv = (const float*)d_in[5];
    const float* wo = (const float*)d_in[6];
    const float* w_gate = (const float*)d_in[7];
    const float* w_up = (const float*)d_in[8];
    const float* w_down = (const float*)d_in[9];
    const float* ln1 = (const float*)d_in[10];
    const float* ln2 = (const float*)d_in[11];
    const float* apw = (const float*)d_in[12];
    const float* apb = (const float*)d_in[13];
    const float* mpw = (const float*)d_in[14];
    const float* mpb = (const float*)d_in[15];
    float* out = (float*)d_out;

    float *hs, *q, *k, *v, *attn, *res2, *hlog, *hmask, *mlog, *fcm, *gate, *up;
    cudaGetSymbolAddress((void**)&hs, g_hs);
    cudaGetSymbolAddress((void**)&q, g_q);
    cudaGetSymbolAddress((void**)&k, g_k);
    cudaGetSymbolAddress((void**)&v, g_v);
    cudaGetSymbolAddress((void**)&attn, g_attn);
    cudaGetSymbolAddress((void**)&res2, g_res2);
    cudaGetSymbolAddress((void**)&hlog, g_hlogit);
    cudaGetSymbolAddress((void**)&hmask, g_headmask);
    cudaGetSymbolAddress((void**)&mlog, g_mlogit);
    cudaGetSymbolAddress((void**)&fcm, g_fcmask);
    cudaGetSymbolAddress((void**)&gate, g_gate);
    cudaGetSymbolAddress((void**)&up, g_up);

    dim3 gHH(HH / 128, TT / 128);   // N=4096 GEMMs
    dim3 gII(II / 128, TT / 128);   // N=11008 GEMMs

    // 1) ln1
    rmsnorm_kernel<<<TT, 256>>>(hidden, ln1, hs);
    // 2) q,k,v projections
    sgemm_nt_kernel<<<gHH, 256>>>(hs, wq, nullptr, nullptr, q, TT, HH, HH);
    sgemm_nt_kernel<<<gHH, 256>>>(hs, wk, nullptr, nullptr, k, TT, HH, HH);
    sgemm_nt_kernel<<<gHH, 256>>>(hs, wv, nullptr, nullptr, v, TT, HH, HH);
    // 3) rope on q,k
    rope_kernel<<<(TT * NH * 64 + 255) / 256, 256>>>(q, k, pos);
    // 4) head predictor + top-16 mask
    attn_pred_kernel<<<TT, 256>>>(hs, apw, apb, hlog);
    head_mask_kernel<<<TT, 32>>>(hlog, hmask);
    // 5) attention (masked heads skipped, write 0)
    attention_kernel<<<dim3(TT, NH), 128>>>(q, k, v, hmask, amask, attn);
    // 6) output projection + residual
    sgemm_nt_kernel<<<gHH, 256>>>(attn, wo, nullptr, hidden, res2, TT, HH, HH);
    // 7) ln2 (reuse hs buffer)
    rmsnorm_kernel<<<TT, 256>>>(res2, ln2, hs);
    // 8) mlp predictor logits + top-2048 mask
    sgemm_nt_kernel<<<gII, 256>>>(hs, mpw, mpb, nullptr, mlog, TT, II, HH);
    mlp_topk_kernel<<<TT, 256>>>(mlog, fcm);
    // 9) gate/up
    sgemm_nt_kernel<<<gII, 256>>>(hs, w_gate, nullptr, nullptr, gate, TT, II, HH);
    sgemm_nt_kernel<<<gII, 256>>>(hs, w_up, nullptr, nullptr, up, TT, II, HH);
    // 10) silu * up * mask
    silu_mul_mask_kernel<<<(TT * II + 255) / 256, 256>>>(gate, up, fcm, TT * II);
    // 11) down projection + residual -> out
    sgemm_nt_kernel<<<gHH, 256>>>(gate, w_down, nullptr, res2, out, TT, HH, II);
}